// round 12
// baseline (speedup 1.0000x reference)
#include <cuda_runtime.h>
#include <math.h>

// Problem constants
#define CB   2
#define CS   2048
#define CD   1024
#define CH   16
#define CDK  64
#define BIAS_LEN (2*CS - 1)   // 4095 relative distances

typedef unsigned long long u64;

// ---------------- packed f32x2 helpers (sm_103a FFMA2 path) ----------------
__device__ __forceinline__ u64 pack2(float lo, float hi) {
    u64 r; asm("mov.b64 %0, {%1, %2};" : "=l"(r) : "f"(lo), "f"(hi)); return r;
}
__device__ __forceinline__ void unpack2(u64 v, float& lo, float& hi) {
    asm("mov.b64 {%0, %1}, %2;" : "=f"(lo), "=f"(hi) : "l"(v));
}
__device__ __forceinline__ void fma2(u64& d, u64 a, u64 b) {
    asm("fma.rn.f32x2 %0, %1, %2, %3;" : "=l"(d) : "l"(a), "l"(b), "l"(d));
}
__device__ __forceinline__ u64 mul2(u64 a, u64 b) {
    u64 r; asm("mul.rn.f32x2 %0, %1, %2;" : "=l"(r) : "l"(a), "l"(b)); return r;
}

// ---------------- scratch (static device globals; no runtime allocation) ----
__device__ __align__(16) float g_Q[(size_t)CB*CH*CS*CDK];
__device__ __align__(16) float g_K[(size_t)CB*CH*CS*CDK];
__device__ __align__(16) float g_V[(size_t)CB*CH*CS*CDK];
__device__ __align__(16) float g_AO[(size_t)CB*CS*CD];
__device__ __align__(16) float g_bias[CH*BIAS_LEN];

// ---------------- T5 relative position bias table --------------------------
__global__ void bias_table_kernel(const float* __restrict__ rel_bias)
{
    int idx = blockIdx.x * blockDim.x + threadIdx.x;
    if (idx >= CH * BIAS_LEN) return;
    int h = idx / BIAS_LEN;
    int t = idx - h * BIAS_LEN;
    int d = t - (CS - 1);

    int base = (d > 0) ? 16 : 0;
    int a = (d < 0) ? -d : d;
    int bucket;
    if (a < 8) {
        bucket = a;
    } else {
        float v = logf((float)a * 0.125f);
        v = v / 2.772588722239781f;     // ln(16)
        v = v * 8.0f;
        int bl = 8 + (int)v;
        bucket = (bl > 15) ? 15 : bl;
    }
    g_bias[h * BIAS_LEN + t] = rel_bias[(base + bucket) * CH + h];
}

// ---------------- SGEMM: 128x128 block, BK=8, 8x8 micro-tile, f32x2 --------
#define GBM 128
#define GBN 128
#define GBK 8

__device__ __forceinline__ void sgemm_body(
    const float* __restrict__ A, const float* __restrict__ W,
    float* __restrict__ C, int N, int K, int scatter)
{
    __shared__ float Asd[GBK][2*GBM];   // A duplicated: Asd[k][2r]=Asd[k][2r+1]
    __shared__ float Bs[GBK][GBN];
    const int tid = threadIdx.x;        // 256 threads
    const int tx = tid & 15;
    const int ty = tid >> 4;
    const float* Ab = A + (size_t)blockIdx.y * GBM * K;
    const float* Wb = W + blockIdx.x * GBN;

    u64 acc[8][4];                      // pairs along j: cols 8tx+2j2, 8tx+2j2+1
    #pragma unroll
    for (int i = 0; i < 8; i++)
        #pragma unroll
        for (int j = 0; j < 4; j++) acc[i][j] = 0ULL;

    const int aRow = tid >> 1;          // 0..127
    const int aCol = (tid & 1) << 2;    // 0 or 4
    const int bRow = tid >> 5;          // 0..7
    const int bCol = (tid & 31) << 2;   // 0..124

    for (int k0 = 0; k0 < K; k0 += GBK) {
        float4 a4 = *(const float4*)(Ab + (size_t)aRow * K + k0 + aCol);
        *(u64*)&Asd[aCol + 0][2*aRow] = pack2(a4.x, a4.x);
        *(u64*)&Asd[aCol + 1][2*aRow] = pack2(a4.y, a4.y);
        *(u64*)&Asd[aCol + 2][2*aRow] = pack2(a4.z, a4.z);
        *(u64*)&Asd[aCol + 3][2*aRow] = pack2(a4.w, a4.w);
        *(float4*)(&Bs[bRow][bCol]) =
            *(const float4*)(Wb + (size_t)(k0 + bRow) * N + bCol);
        __syncthreads();
        #pragma unroll
        for (int kk = 0; kk < GBK; kk++) {
            const ulonglong2* ap = (const ulonglong2*)&Asd[kk][16 * ty];
            ulonglong2 a01 = ap[0], a23 = ap[1], a45 = ap[2], a67 = ap[3];
            const ulonglong2* bp = (const ulonglong2*)&Bs[kk][8 * tx];
            ulonglong2 b01 = bp[0], b23 = bp[1];
            u64 ar[8] = {a01.x, a01.y, a23.x, a23.y, a45.x, a45.y, a67.x, a67.y};
            u64 br[4] = {b01.x, b01.y, b23.x, b23.y};
            #pragma unroll
            for (int i = 0; i < 8; i++)
                #pragma unroll
                for (int j = 0; j < 4; j++)
                    fma2(acc[i][j], ar[i], br[j]);
        }
        __syncthreads();
    }

    #pragma unroll
    for (int i = 0; i < 8; i++) {
        float c[8];
        unpack2(acc[i][0], c[0], c[1]);
        unpack2(acc[i][1], c[2], c[3]);
        unpack2(acc[i][2], c[4], c[5]);
        unpack2(acc[i][3], c[6], c[7]);
        int m = blockIdx.y * GBM + ty * 8 + i;
        float* Crow;
        if (!scatter) {
            Crow = C + (size_t)m * N + blockIdx.x * GBN + tx * 8;
        } else {
            int b = m >> 11;
            int s = m & (CS - 1);
            int n = blockIdx.x * GBN + tx * 8;   // 8 cols stay inside one head
            int h = n >> 6;
            int dk = n & 63;
            Crow = C + ((((size_t)b * CH + h) * CS + s) * CDK + dk);
        }
        *(float4*)(Crow)     = make_float4(c[0], c[1], c[2], c[3]);
        *(float4*)(Crow + 4) = make_float4(c[4], c[5], c[6], c[7]);
    }
}

__global__ void __launch_bounds__(256) qkv_kernel(
    const float* __restrict__ X,
    const float* __restrict__ Wq, const float* __restrict__ Wk,
    const float* __restrict__ Wv)
{
    const float* W = (blockIdx.z == 0) ? Wq : (blockIdx.z == 1) ? Wk : Wv;
    float* O = (blockIdx.z == 0) ? g_Q : (blockIdx.z == 1) ? g_K : g_V;
    sgemm_body(X, W, O, CD, CD, 1);
}

__global__ void __launch_bounds__(256) out_proj_kernel(
    const float* __restrict__ Wo, float* __restrict__ out)
{
    sgemm_body(g_AO, Wo, out, CD, CD, 0);
}

// ---------------- fused flash attention (fp32, f32x2, online softmax) ------
#define AQ  64          // q rows per block
#define AK  64          // k rows per tile
#define ALD 68          // padded smem row for Ks/Vs
#define DLD 132         // padded row for duplicated Qsd/Psd (2*64 + 4)

struct AttnSmem {
    float Qsd[CDK][DLD];  // duplicated Q transposed: Qsd[d][2r]=Qsd[d][2r+1]
    float Ks[CDK][ALD];   // K transposed: Ks[d][c]
    float Vs[AK][ALD];    // Vs[kk][d]
    float Psd[AQ][DLD];   // duplicated probabilities: Psd[r][2kk]=Psd[r][2kk+1]
    float bias[CS + AQ];  // bias slice for this q-tile
};

__global__ void __launch_bounds__(256) attn_kernel()
{
    extern __shared__ char smem_raw[];
    AttnSmem* sm = reinterpret_cast<AttnSmem*>(smem_raw);

    const int tid = threadIdx.x;       // 256 threads: 16x16, 4x4 micro-tiles
    const int tx = tid & 15;
    const int ty = tid >> 4;
    const int i0 = blockIdx.x * AQ;
    const int h  = blockIdx.y;
    const int b  = blockIdx.z;

    const size_t head_off = ((size_t)b * CH + h) * CS * CDK;
    const float* Qg = g_Q + head_off + (size_t)i0 * CDK;
    const float* Kg = g_K + head_off;
    const float* Vg = g_V + head_off;

    // load Q tile transposed + duplicated: Qsd[d][2r],[2r+1]
    for (int v = tid; v < AQ * (CDK / 4); v += 256) {
        int r  = v >> 4;
        int d4 = (v & 15) << 2;
        float4 q4 = *(const float4*)(Qg + r * CDK + d4);
        *(u64*)&sm->Qsd[d4 + 0][2*r] = pack2(q4.x, q4.x);
        *(u64*)&sm->Qsd[d4 + 1][2*r] = pack2(q4.y, q4.y);
        *(u64*)&sm->Qsd[d4 + 2][2*r] = pack2(q4.z, q4.z);
        *(u64*)&sm->Qsd[d4 + 3][2*r] = pack2(q4.w, q4.w);
    }
    // load bias slice (same indexing as the passing round-10 kernel)
    for (int t = tid; t < CS - 1 + AQ; t += 256)
        sm->bias[t] = g_bias[h * BIAS_LEN + t + CS - i0 - AQ];

    float m[4], l[4];
    u64 o2[4][2];                       // o pairs along j: cols 4tx+2j2, +1
    #pragma unroll
    for (int i = 0; i < 4; i++) {
        m[i] = -1e30f;
        l[i] = 0.f;
        o2[i][0] = 0ULL; o2[i][1] = 0ULL;
    }

    for (int kt = 0; kt < CS / AK; kt++) {
        const int kj0 = kt * AK;
        __syncthreads();   // prev-iter PV done with Psd/Vs

        // load K (transposed) + V tiles
        for (int v = tid; v < AK * (CDK / 4); v += 256) {
            int row = v >> 4;
            int d4  = (v & 15) << 2;
            float4 k4 = *(const float4*)(Kg + (size_t)(kj0 + row) * CDK + d4);
            sm->Ks[d4 + 0][row] = k4.x;
            sm->Ks[d4 + 1][row] = k4.y;
            sm->Ks[d4 + 2][row] = k4.z;
            sm->Ks[d4 + 3][row] = k4.w;
            *(float4*)&sm->Vs[row][d4] =
                *(const float4*)(Vg + (size_t)(kj0 + row) * CDK + d4);
        }
        __syncthreads();

        // S = Q @ K^T  -- f32x2, pairs along j (K naturally paired)
        u64 s2[4][2];
        #pragma unroll
        for (int i = 0; i < 4; i++) { s2[i][0] = 0ULL; s2[i][1] = 0ULL; }

        #pragma unroll 8
        for (int d = 0; d < CDK; d++) {
            const ulonglong2 q01 = *(const ulonglong2*)&sm->Qsd[d][8 * ty];
            const ulonglong2 q23 = *(const ulonglong2*)&sm->Qsd[d][8 * ty + 4];
            const ulonglong2 kk2 = *(const ulonglong2*)&sm->Ks[d][4 * tx];
            u64 qd[4] = {q01.x, q01.y, q23.x, q23.y};
            #pragma unroll
            for (int i = 0; i < 4; i++) {
                fma2(s2[i][0], qd[i], kk2.x);
                fma2(s2[i][1], qd[i], kk2.y);
            }
        }

        // unpack scores
        float s[4][4];
        #pragma unroll
        for (int i = 0; i < 4; i++) {
            unpack2(s2[i][0], s[i][0], s[i][1]);
            unpack2(s2[i][1], s[i][2], s[i][3]);
        }

        // + position bias (T5: no 1/sqrt(dk) scaling)
        #pragma unroll
        for (int i = 0; i < 4; i++) {
            int tb = kj0 + tx * 4 + (AQ - 1) - (ty * 4 + i);
            #pragma unroll
            for (int j = 0; j < 4; j++)
                s[i][j] += sm->bias[tb + j];
        }

        // online softmax: rows owned by 16 lanes with same ty
        #pragma unroll
        for (int i = 0; i < 4; i++) {
            float mloc = fmaxf(fmaxf(s[i][0], s[i][1]), fmaxf(s[i][2], s[i][3]));
            #pragma unroll
            for (int off = 8; off >= 1; off >>= 1)
                mloc = fmaxf(mloc, __shfl_xor_sync(0xffffffffu, mloc, off));
            float mnew = fmaxf(m[i], mloc);
            float sc = __expf(m[i] - mnew);
            m[i] = mnew;
            float ps = 0.f;
            #pragma unroll
            for (int j = 0; j < 4; j++) {
                float p = __expf(s[i][j] - mnew);
                s[i][j] = p;
                ps += p;
            }
            #pragma unroll
            for (int off = 8; off >= 1; off >>= 1)
                ps += __shfl_xor_sync(0xffffffffu, ps, off);
            l[i] = l[i] * sc + ps;
            u64 sc2 = pack2(sc, sc);
            o2[i][0] = mul2(o2[i][0], sc2);
            o2[i][1] = mul2(o2[i][1], sc2);
        }

        // stash probabilities duplicated: Psd[r][2k]=Psd[r][2k+1]=p
        #pragma unroll
        for (int i = 0; i < 4; i++) {
            *(float4*)&sm->Psd[ty * 4 + i][8 * tx] =
                make_float4(s[i][0], s[i][0], s[i][1], s[i][1]);
            *(float4*)&sm->Psd[ty * 4 + i][8 * tx + 4] =
                make_float4(s[i][2], s[i][2], s[i][3], s[i][3]);
        }
        __syncthreads();

        // O += P @ V  -- f32x2, V naturally paired, P broadcast via dup LDS.64
        #pragma unroll 8
        for (int kk = 0; kk < AK; kk++) {
            const ulonglong2 v2 = *(const ulonglong2*)&sm->Vs[kk][4 * tx];
            u64 p0 = *(const u64*)&sm->Psd[ty * 4 + 0][2 * kk];
            u64 p1 = *(const u64*)&sm->Psd[ty * 4 + 1][2 * kk];
            u64 p2 = *(const u64*)&sm->Psd[ty * 4 + 2][2 * kk];
            u64 p3 = *(const u64*)&sm->Psd[ty * 4 + 3][2 * kk];
            fma2(o2[0][0], p0, v2.x); fma2(o2[0][1], p0, v2.y);
            fma2(o2[1][0], p1, v2.x); fma2(o2[1][1], p1, v2.y);
            fma2(o2[2][0], p2, v2.x); fma2(o2[2][1], p2, v2.y);
            fma2(o2[3][0], p3, v2.x); fma2(o2[3][1], p3, v2.y);
        }
    }

    // epilogue: normalize, write [b, s, h*64+dk] (ready for Wo GEMM)
    #pragma unroll
    for (int i = 0; i < 4; i++) {
        float inv = 1.f / l[i];
        float o0, o1, o2v, o3;
        unpack2(o2[i][0], o0, o1);
        unpack2(o2[i][1], o2v, o3);
        int srow = i0 + ty * 4 + i;
        float* dst = g_AO + ((size_t)b * CS + srow) * CD + h * CDK + tx * 4;
        *(float4*)dst = make_float4(o0 * inv, o1 * inv, o2v * inv, o3 * inv);
    }
}

// ---------------- launch ----------------------------------------------------
extern "C" void kernel_launch(void* const* d_in, const int* in_sizes, int n_in,
                              void* d_out, int out_size)
{
    (void)in_sizes; (void)n_in; (void)out_size;
    const float* X  = (const float*)d_in[0];
    const float* Wq = (const float*)d_in[1];
    const float* Wk = (const float*)d_in[2];
    const float* Wv = (const float*)d_in[3];
    const float* Wo = (const float*)d_in[4];
    const float* rb = (const float*)d_in[5];
    float* out = (float*)d_out;

    // 1) relative-position bias table
    {
        int total = CH * BIAS_LEN;
        bias_table_kernel<<<(total + 255) / 256, 256>>>(rb);
    }
    // 2) fused QKV projections
    {
        dim3 grid(CD / GBN, (CB * CS) / GBM, 3);
        qkv_kernel<<<grid, 256>>>(X, Wq, Wk, Wv);
    }
    // 3) fused flash attention
    {
        cudaFuncSetAttribute(attn_kernel,
                             cudaFuncAttributeMaxDynamicSharedMemorySize,
                             (int)sizeof(AttnSmem));
        dim3 grid(CS / AQ, CH, CB);
        attn_kernel<<<grid, 256, sizeof(AttnSmem)>>>();
    }
    // 4) output projection -> d_out
    {
        dim3 grid(CD / GBN, (CB * CS) / GBM);
        out_proj_kernel<<<grid, 256>>>(Wo, out);
    }
}